// round 10
// baseline (speedup 1.0000x reference)
#include <cuda_runtime.h>
#include <cstdint>

// GenODE: z' = tanh(z W1^T + b1) W2^T + b2, N=8192 rows, D=64, H=128.
// Fixed-step RK4, dt = 1/63, one step per output interval.
//
// R10 = R9 (P=16 threads/row, 4 rows/thread, 256 thr/CTA, grid=128) with
// the W2 stage restructured to eliminate its 512 pack2 movs/thread:
//  * accumulate row-pair-packed (k_d^A, k_d^B) via fma.rn.f32x2
//  * activation operand (h_j^A, h_j^B) loaded directly from a row-pair
//    interleaved staging buffer (no duplication movs)
//  * W2 weights duplicated (w,w) STATICALLY in SMEM (dup layout, slice
//    stride 12 -> conflict-free 2-wavefront LDS.128, 16B aligned)
// W1 keeps the R9 d-pair packing (mov ratio 1:4 is acceptable there).
// Summation order over j unchanged -> arithmetic identical to R9.

#define NROWS 8192
#define TPTS  64

#define SW1_OFS  0
#define SW2D_OFS 12288        // 64*192
#define SB1_OFS  36864        // + 128*192
#define SB2D_OFS 37056        // + 16*12
#define YB_OFS   37248        // + 16*12
#define HBI_OFS  41600        // + 8 warps * 544
#define SMEM_FLOATS 50048     // + 8 warps * 1056

typedef unsigned long long ull;

__device__ __forceinline__ ull pack2(float a, float b) {
    ull r; asm("mov.b64 %0, {%1, %2};" : "=l"(r) : "f"(a), "f"(b)); return r;
}
__device__ __forceinline__ void unpack2(ull v, float& a, float& b) {
    asm("mov.b64 {%0, %1}, %2;" : "=f"(a), "=f"(b) : "l"(v));
}
__device__ __forceinline__ ull fma2(ull a, ull b, ull c) {
    ull d; asm("fma.rn.f32x2 %0, %1, %2, %3;" : "=l"(d) : "l"(a), "l"(b), "l"(c));
    return d;
}

__device__ __forceinline__ float tanh_fast(float x) {
    float e = __expf(2.0f * x);
    return __fdividef(e - 1.0f, e + 1.0f);
}

// y[i][0..3]: z-slice (dims [4s,4s+4)) of stage input for the thread's 4
// rows (r = g + 2i). k[i][0..3]: f(y) slice out.
__device__ __forceinline__ void eval4(
    const float* __restrict__ sW1, const float* __restrict__ sW2d,
    const float* __restrict__ sb1, const float* __restrict__ sb2d,
    float* __restrict__ yb, float* __restrict__ hbi,
    int g, int s,
    const float y[4][4], float k[4][4])
{
    // ---- stage y slices ----
    #pragma unroll
    for (int i = 0; i < 4; i++) {
        int r = g + 2 * i;
        *(float4*)(yb + r * 68 + s * 4) =
            make_float4(y[i][0], y[i][1], y[i][2], y[i][3]);
    }
    __syncwarp();

    // ---- h = b1 + W1 y : 8 h per thread per row, d-pair packed ----
    ull h[4][4];
    {
        const ull* bp = (const ull*)(sb1 + s * 12);
        ull b0 = bp[0], b1v = bp[1], b2v = bp[2], b3 = bp[3];
        #pragma unroll
        for (int i = 0; i < 4; i++) {
            h[i][0] = b0; h[i][1] = b1v; h[i][2] = b2v; h[i][3] = b3;
        }
    }
    {
        const float* wr = sW1 + s * 12;
        #pragma unroll 4
        for (int c = 0; c < 16; c++) {
            float4 yv[4];
            #pragma unroll
            for (int i = 0; i < 4; i++)
                yv[i] = *(const float4*)(yb + (g + 2 * i) * 68 + c * 4);
            #pragma unroll
            for (int t = 0; t < 4; t++) {
                const ulonglong2* w = (const ulonglong2*)(wr + (c * 4 + t) * 192);
                ulonglong2 w0 = w[0], w1 = w[1];
                #pragma unroll
                for (int i = 0; i < 4; i++) {
                    float zv = (t == 0) ? yv[i].x : (t == 1) ? yv[i].y
                             : (t == 2) ? yv[i].z : yv[i].w;
                    ull zz = pack2(zv, zv);
                    h[i][0] = fma2(w0.x, zz, h[i][0]);
                    h[i][1] = fma2(w0.y, zz, h[i][1]);
                    h[i][2] = fma2(w1.x, zz, h[i][2]);
                    h[i][3] = fma2(w1.y, zz, h[i][3]);
                }
            }
        }
    }

    // ---- tanh, stage h row-pair interleaved: pair p holds rows
    //      A = g+4p (i=2p), B = g+4p+2 (i=2p+1) as (hA,hB,hA,hB,...) ----
    #pragma unroll
    for (int p = 0; p < 2; p++) {
        float ha[8], hbv[8];
        #pragma unroll
        for (int m = 0; m < 4; m++) {
            float a0, a1, b0, b1v;
            unpack2(h[2*p+0][m], a0, a1);
            unpack2(h[2*p+1][m], b0, b1v);
            ha[2*m+0]  = tanh_fast(a0);
            ha[2*m+1]  = tanh_fast(a1);
            hbv[2*m+0] = tanh_fast(b0);
            hbv[2*m+1] = tanh_fast(b1v);
        }
        float4* q = (float4*)(hbi + (g * 2 + p) * 264 + s * 16);
        q[0] = make_float4(ha[0], hbv[0], ha[1], hbv[1]);
        q[1] = make_float4(ha[2], hbv[2], ha[3], hbv[3]);
        q[2] = make_float4(ha[4], hbv[4], ha[5], hbv[5]);
        q[3] = make_float4(ha[6], hbv[6], ha[7], hbv[7]);
    }
    __syncwarp();

    // ---- k = b2 + W2 h : row-pair packed (k_d^A, k_d^B), dup weights ----
    ull kpp[2][4];
    {
        const ulonglong2* bp = (const ulonglong2*)(sb2d + s * 12);
        ulonglong2 b01 = bp[0], b23 = bp[1];
        #pragma unroll
        for (int p = 0; p < 2; p++) {
            kpp[p][0] = b01.x; kpp[p][1] = b01.y;
            kpp[p][2] = b23.x; kpp[p][3] = b23.y;
        }
    }
    {
        const float* wr = sW2d + s * 12;
        #pragma unroll 4
        for (int c = 0; c < 64; c++) {            // j = 2c, 2c+1
            const ulonglong2* wap = (const ulonglong2*)(wr + (2 * c + 0) * 192);
            const ulonglong2* wbp = (const ulonglong2*)(wr + (2 * c + 1) * 192);
            ulonglong2 wa0 = wap[0], wa1 = wap[1];  // j=2c  : (d0,d0),(d1,d1),(d2,d2),(d3,d3)
            ulonglong2 wb0 = wbp[0], wb1 = wbp[1];  // j=2c+1
            #pragma unroll
            for (int p = 0; p < 2; p++) {
                const ulonglong2* hp =
                    (const ulonglong2*)(hbi + (g * 2 + p) * 264 + c * 4);
                ulonglong2 hu = hp[0];  // x=(hA_{2c},hB_{2c}) y=(hA_{2c+1},hB_{2c+1})
                kpp[p][0] = fma2(wa0.x, hu.x, kpp[p][0]);
                kpp[p][1] = fma2(wa0.y, hu.x, kpp[p][1]);
                kpp[p][2] = fma2(wa1.x, hu.x, kpp[p][2]);
                kpp[p][3] = fma2(wa1.y, hu.x, kpp[p][3]);
                kpp[p][0] = fma2(wb0.x, hu.y, kpp[p][0]);
                kpp[p][1] = fma2(wb0.y, hu.y, kpp[p][1]);
                kpp[p][2] = fma2(wb1.x, hu.y, kpp[p][2]);
                kpp[p][3] = fma2(wb1.y, hu.y, kpp[p][3]);
            }
        }
    }
    #pragma unroll
    for (int p = 0; p < 2; p++)
        #pragma unroll
        for (int m = 0; m < 4; m++)
            unpack2(kpp[p][m], k[2*p+0][m], k[2*p+1][m]);
}

__global__ void __launch_bounds__(256, 1)
ode_kernel(const float* __restrict__ rand_e,
           const float* __restrict__ z0_mean,
           const float* __restrict__ z0_log_sigma,
           const float* __restrict__ W1,
           const float* __restrict__ b1,
           const float* __restrict__ W2,
           const float* __restrict__ b2,
           float* __restrict__ out,
           long long z0_off, long long t_off, long long z_off)
{
    extern __shared__ float sm[];
    float* sW1  = sm + SW1_OFS;
    float* sW2d = sm + SW2D_OFS;
    float* sb1  = sm + SB1_OFS;
    float* sb2d = sm + SB2D_OFS;
    int tid = threadIdx.x;

    // W1: (H=128, D=64) row-major -> sW1[d*192 + (j>>3)*12 + (j&7)]
    for (int idx = tid; idx < 128 * 64; idx += 256) {
        int j = idx >> 6, d = idx & 63;
        sW1[d * 192 + (j >> 3) * 12 + (j & 7)] = W1[idx];
    }
    // W2 dup: (D=64, H=128) row-major -> sW2d[j*192 + (d>>2)*12 + (d&3)*2 + {0,1}]
    for (int idx = tid; idx < 64 * 128; idx += 256) {
        int d = idx >> 7, j = idx & 127;
        int off = j * 192 + (d >> 2) * 12 + (d & 3) * 2;
        float v = W2[idx];
        sW2d[off] = v; sW2d[off + 1] = v;
    }
    if (tid < 128)      sb1[(tid >> 3) * 12 + (tid & 7)] = b1[tid];
    else if (tid < 192) {
        int d = tid - 128;
        int off = (d >> 2) * 12 + (d & 3) * 2;
        float v = b2[d];
        sb2d[off] = v; sb2d[off + 1] = v;
    }
    __syncthreads();

    int lane = tid & 31;
    int g = lane & 1;        // row-parity within warp
    int s = lane >> 1;       // slice: z dims [4s,4s+4), h dims [8s,8s+8)
    int warp = tid >> 5;
    float* yb  = sm + YB_OFS  + warp * 544;    // 8 rows * 68
    float* hbi = sm + HBI_OFS + warp * 1056;   // 4 pair-rows * 264
    int rbase = blockIdx.x * 64 + warp * 8;

    if (t_off >= 0 && blockIdx.x == 0 && tid < TPTS)
        out[t_off + tid] = (float)tid * (1.0f / 63.0f);

    float sig = expf(z0_log_sigma[0]);
    float z[4][4];
    {
        float4 zm = *(const float4*)(z0_mean + s * 4);
        #pragma unroll
        for (int i = 0; i < 4; i++) {
            int r = rbase + g + 2 * i;
            float4 rv = *(const float4*)(rand_e + (size_t)r * 64 + s * 4);
            z[i][0] = zm.x + sig * rv.x;
            z[i][1] = zm.y + sig * rv.y;
            z[i][2] = zm.z + sig * rv.z;
            z[i][3] = zm.w + sig * rv.w;
        }
    }

    size_t lofs[4];
    #pragma unroll
    for (int i = 0; i < 4; i++)
        lofs[i] = (size_t)(rbase + g + 2 * i) * 64 + s * 4;

    if (z0_off >= 0) {
        #pragma unroll
        for (int i = 0; i < 4; i++)
            *(float4*)(out + z0_off + lofs[i]) =
                make_float4(z[i][0], z[i][1], z[i][2], z[i][3]);
    }
    #pragma unroll
    for (int i = 0; i < 4; i++)   // z at t=0 equals z0
        *(float4*)(out + z_off + lofs[i]) =
            make_float4(z[i][0], z[i][1], z[i][2], z[i][3]);

    const float dt = 1.0f / 63.0f;
    #pragma unroll 1
    for (int step = 0; step < 63; step++) {
        float acc[4][4], y[4][4];
        #pragma unroll
        for (int i = 0; i < 4; i++)
            #pragma unroll
            for (int t = 0; t < 4; t++) {
                y[i][t] = z[i][t];
                acc[i][t] = 0.0f;
            }
        #pragma unroll 1
        for (int st = 0; st < 4; st++) {
            float k[4][4];
            eval4(sW1, sW2d, sb1, sb2d, yb, hbi, g, s, y, k);
            float bw = (st == 1 || st == 2) ? 2.0f : 1.0f;
            float aw = (st == 2) ? dt : ((st == 3) ? 0.0f : 0.5f * dt);
            #pragma unroll
            for (int i = 0; i < 4; i++)
                #pragma unroll
                for (int t = 0; t < 4; t++) {
                    acc[i][t] += bw * k[i][t];
                    y[i][t]   = z[i][t] + aw * k[i][t];
                }
        }
        #pragma unroll
        for (int i = 0; i < 4; i++)
            #pragma unroll
            for (int t = 0; t < 4; t++)
                z[i][t] += (dt * (1.0f / 6.0f)) * acc[i][t];

        size_t tofs = z_off + (size_t)(step + 1) * (NROWS * 64);
        #pragma unroll
        for (int i = 0; i < 4; i++)
            *(float4*)(out + tofs + lofs[i]) =
                make_float4(z[i][0], z[i][1], z[i][2], z[i][3]);
    }
}

extern "C" void kernel_launch(void* const* d_in, const int* in_sizes, int n_in,
                              void* d_out, int out_size)
{
    const float* rand_e       = (const float*)d_in[0];
    const float* z0_mean      = (const float*)d_in[1];
    const float* z0_log_sigma = (const float*)d_in[2];
    const float* W1           = (const float*)d_in[3];
    const float* b1           = (const float*)d_in[4];
    const float* W2           = (const float*)d_in[5];
    const float* b2           = (const float*)d_in[6];

    const long long Z0SZ = (long long)NROWS * 64;   // 524288
    const long long TSZ  = TPTS;                    // 64
    const long long ZSZ  = (long long)TPTS * NROWS * 64;

    long long z0_off, t_off, z_off;
    long long osz = (long long)out_size;
    if (osz == Z0SZ + TSZ + ZSZ)      { z0_off = 0;  t_off = Z0SZ; z_off = Z0SZ + TSZ; }
    else if (osz == ZSZ)              { z0_off = -1; t_off = -1;   z_off = 0; }
    else if (osz == Z0SZ + ZSZ)       { z0_off = 0;  t_off = -1;   z_off = Z0SZ; }
    else                              { z0_off = 0;  t_off = Z0SZ; z_off = Z0SZ + TSZ; }

    cudaFuncSetAttribute(ode_kernel,
                         cudaFuncAttributeMaxDynamicSharedMemorySize,
                         SMEM_FLOATS * sizeof(float));

    ode_kernel<<<NROWS / 64, 256, SMEM_FLOATS * sizeof(float)>>>(
        rand_e, z0_mean, z0_log_sigma, W1, b1, W2, b2,
        (float*)d_out, z0_off, t_off, z_off);
}